// round 17
// baseline (speedup 1.0000x reference)
#include <cuda_runtime.h>
#include <cuda_fp16.h>
#include <cstdint>

#define KC    64
#define DCOL  1024
#define NTRI  2016
#define NEVEN 1024
#define NM3   512
#define NM4   512
#define NM5   512
#define TPB   128
#define TROWS 128
#define NTILES 256
#define NCTA  2048          // 8 CTAs per tile; each gathers 16 rows + one term-eighth
#define NMQ   64            // terms per table per CTA

__device__ uint2  g_rec3[NM3];
__device__ uint2  g_rec4[NM4];
__device__ uint4  g_rec5[NM5];
__device__ __half g_xs[NTILES * KC * TROWS];   // [tile][col][row]
__device__ int    g_cnt[NTILES];               // readiness (8 segs + records = 9)
__device__ int    g_fin[NTILES];               // consumption (8 -> reset)

__device__ __forceinline__ int base_e(int m) { return m * (64 - m); }
__device__ __forceinline__ int base_o(int m) { return m * (63 - m); }

__device__ __forceinline__ __half2 as_h2(unsigned u) {
    __half2 h; *reinterpret_cast<unsigned*>(&h) = u; return h;
}
__device__ __forceinline__ float xat(const unsigned* v, int j) {
    __half2 h = as_h2(v[j >> 1]);
    return (j & 1) ? __high2float(h) : __low2float(h);
}

template<int H>
__device__ __forceinline__ float quadf16(const float* s_tri, const unsigned* xv2)
{
    const float4* tri4 = (const float4*)s_tri;
    float4 tb = make_float4(0.f,0.f,0.f,0.f);
    float acc = 0.f;
    int p = H ? NEVEN : 0;
    #pragma unroll
    for (int i = H; i < KC - 1; i += 2) {
        float s = 0.f;
        #pragma unroll
        for (int j = i + 1; j < KC; ++j) {
            if ((p & 3) == 0) tb = tri4[p >> 2];
            float bv = ((p&3)==0)?tb.x:((p&3)==1)?tb.y:((p&3)==2)?tb.z:tb.w;
            s = fmaf(bv, xat(xv2, j), s);
            ++p;
        }
        acc = fmaf(s, xat(xv2, i), acc);
    }
    return acc;
}

__global__ __launch_bounds__(TPB)
void fused_kernel(const float* __restrict__ x, float* __restrict__ out,
                  const float* __restrict__ b, const int* __restrict__ S,
                  const float* __restrict__ a,
                  const int* __restrict__ idx3, const float* __restrict__ c3,
                  const int* __restrict__ idx4, const float* __restrict__ c4,
                  const int* __restrict__ idx5, const float* __restrict__ c5)
{
    __shared__ __align__(16) char sm[18432];
    const int tid  = threadIdx.x;
    const int tile = blockIdx.x >> 3;
    const int seg  = blockIdx.x & 7;

    // ---------- phase 1: records (bid 0), triangle, gather, quad ----------
    float*  s_tri   = (float*)sm;                    // 8064 B
    __half* s_stage = (__half*)(sm + 8064);          // [16][68] = 2176 B
    float*  s_qv    = (float*)(sm + 8064 + 2176);    // [2][16]

    if (blockIdx.x == 0) {
        for (int t = tid; t < NM3; t += TPB) {
            unsigned p = (unsigned)idx3[t*3] | ((unsigned)idx3[t*3+1]<<8) | ((unsigned)idx3[t*3+2]<<16);
            uint2 r; r.x = p; r.y = __float_as_uint(c3[t]); g_rec3[t] = r;
        }
        for (int t = tid; t < NM4; t += TPB) {
            unsigned p = (unsigned)idx4[t*4] | ((unsigned)idx4[t*4+1]<<8) | ((unsigned)idx4[t*4+2]<<16) | ((unsigned)idx4[t*4+3]<<24);
            uint2 r; r.x = p; r.y = __float_as_uint(c4[t]); g_rec4[t] = r;
        }
        for (int t = tid; t < NM5; t += TPB) {
            unsigned p = (unsigned)idx5[t*5] | ((unsigned)idx5[t*5+1]<<8) | ((unsigned)idx5[t*5+2]<<16) | ((unsigned)idx5[t*5+3]<<24);
            uint4 r; r.x = p; r.y = (unsigned)idx5[t*5+4]; r.z = __float_as_uint(c5[t]); r.w = 0u;
            g_rec5[t] = r;
        }
        __syncthreads();
        __threadfence();
        atomicAdd(&g_cnt[tid], 1);            // records-ready +1 on all 256 tiles
        atomicAdd(&g_cnt[TPB + tid], 1);
    }

    // parity-packed triangle, batched closed-form (16 slots/thread)
    {
        int dsti[16], srci[16];
        #pragma unroll
        for (int s = 0; s < 16; ++s) {
            int p = tid + s * TPB, i, j;
            if (p < NEVEN) {
                int m = (int)(32.0f - sqrtf((float)(1024 - p)));
                if (m < 0) m = 0; if (m > 31) m = 31;
                while (m > 0  && base_e(m)     > p) --m;
                while (m < 31 && base_e(m + 1) <= p) ++m;
                i = 2*m; j = i + 1 + (p - base_e(m));
            } else {
                int q = p - NEVEN;
                int m = (int)(31.5f - sqrtf(992.25f - (float)q));
                if (m < 0) m = 0; if (m > 30) m = 30;
                while (m > 0  && NEVEN + base_o(m)     > p) --m;
                while (m < 30 && base_o(m + 1) <= q) ++m;
                i = 2*m + 1; j = i + 1 + (q - base_o(m));
            }
            dsti[s] = p; srci[s] = i * 64 + j;
        }
        float v[16];
        #pragma unroll
        for (int s = 0; s < 16; ++s) v[s] = (dsti[s] < NTRI) ? __ldg(b + srci[s]) : 0.f;
        #pragma unroll
        for (int s = 0; s < 16; ++s) if (dsti[s] < NTRI) s_tri[dsti[s]] = v[s];
    }

    // gather 16 rows: 8 threads/row, 8 cols each; stage + spill
    {
        const int r = tid >> 3, c8 = tid & 7;
        const long long grow = (long long)tile * TROWS + seg * 16 + r;
        const float* xr = x + grow * DCOL;
        int cols[8]; float xv[8];
        #pragma unroll
        for (int c = 0; c < 8; ++c) cols[c] = __ldg(S + c8 * 8 + c);
        #pragma unroll
        for (int c = 0; c < 8; ++c) xv[c] = __ldg(xr + cols[c]);
        __half* xt = g_xs + (size_t)tile * (KC * TROWS) + seg * 16 + r;
        #pragma unroll
        for (int c = 0; c < 8; ++c) {
            __half hv = __float2half(xv[c]);
            s_stage[r * 68 + c8 * 8 + c] = hv;
            xt[(size_t)(c8 * 8 + c) * TROWS] = hv;
        }
    }
    __syncthreads();

    // quad: warp 0 = even half, warp 1 = odd half + linear (rows on lanes 0..15)
    {
        const int w = tid >> 5, lane = tid & 31;
        if (w < 2 && lane < 16) {
            const unsigned* rowp = (const unsigned*)(s_stage + lane * 68);
            unsigned xv2[32];
            #pragma unroll
            for (int c = 0; c < 32; ++c) xv2[c] = rowp[c];
            float acc;
            if (w == 0) acc = quadf16<0>(s_tri, xv2);
            else {
                float l = 0.f;
                #pragma unroll
                for (int k = 0; k < KC; ++k) l = fmaf(__ldg(a + k), xat(xv2, k), l);
                acc = l + quadf16<1>(s_tri, xv2);
            }
            s_qv[w * 16 + lane] = acc;
        }
    }
    __syncthreads();
    if (tid < 16)
        out[(long long)tile * TROWS + seg * 16 + tid] = s_qv[tid] + s_qv[16 + tid];

    __threadfence();
    __syncthreads();
    if (tid == 0) atomicAdd(&g_cnt[tile], 1);

    // ---------- phase 2: wait for tile, then mono eighth ----------
    if (tid == 0) {
        while (atomicAdd(&g_cnt[tile], 0) < 9) __nanosleep(64);
    }
    __syncthreads();
    __threadfence();

    __half (*s_x)[TROWS] = (__half(*)[TROWS])sm;           // 16 KB
    float  (*s_redf)[TROWS] = (float(*)[TROWS])(sm + 16384);

    {
        const uint4* src = (const uint4*)(g_xs + (size_t)tile * (KC * TROWS));
        uint4* dst = (uint4*)&s_x[0][0];
        #pragma unroll
        for (int i = 0; i < 8; ++i) dst[tid + i * TPB] = src[tid + i * TPB];
    }
    __syncthreads();

    const int gg = tid & 31, q = tid >> 5;
    const char* xb = (const char*)(&s_x[0][0]) + 8 * gg;
    const int base = seg * NMQ;
    float m0 = 0.f, m1 = 0.f, m2 = 0.f, m3 = 0.f;
    {
        const int lo = base + q * (NMQ/4), hi = lo + (NMQ/4);
        #pragma unroll 4
        for (int t = lo; t < hi; ++t) {
            uint2 r = __ldg(&g_rec3[t]);
            unsigned o0 = (r.x << 8) & 0xFF00u, o1 = r.x & 0xFF00u, o2 = (r.x >> 8) & 0xFF00u;
            uint2 u0 = *(const uint2*)(xb+o0), u1 = *(const uint2*)(xb+o1), u2 = *(const uint2*)(xb+o2);
            __half2 pa = __hmul2(__hmul2(as_h2(u0.x), as_h2(u1.x)), as_h2(u2.x));
            __half2 pb = __hmul2(__hmul2(as_h2(u0.y), as_h2(u1.y)), as_h2(u2.y));
            float2 fa = __half22float2(pa), fb = __half22float2(pb);
            float c = __uint_as_float(r.y);
            m0 = fmaf(c, fa.x, m0); m1 = fmaf(c, fa.y, m1);
            m2 = fmaf(c, fb.x, m2); m3 = fmaf(c, fb.y, m3);
        }
    }
    {
        const int lo = base + q * (NMQ/4), hi = lo + (NMQ/4);
        #pragma unroll 4
        for (int t = lo; t < hi; ++t) {
            uint2 r = __ldg(&g_rec4[t]);
            unsigned o0 = (r.x << 8) & 0xFF00u, o1 = r.x & 0xFF00u;
            unsigned o2 = (r.x >> 8) & 0xFF00u, o3 = (r.x >> 16) & 0xFF00u;
            uint2 u0 = *(const uint2*)(xb+o0), u1 = *(const uint2*)(xb+o1);
            uint2 u2 = *(const uint2*)(xb+o2), u3 = *(const uint2*)(xb+o3);
            __half2 pa = __hmul2(__hmul2(as_h2(u0.x), as_h2(u1.x)), __hmul2(as_h2(u2.x), as_h2(u3.x)));
            __half2 pb = __hmul2(__hmul2(as_h2(u0.y), as_h2(u1.y)), __hmul2(as_h2(u2.y), as_h2(u3.y)));
            float2 fa = __half22float2(pa), fb = __half22float2(pb);
            float c = __uint_as_float(r.y);
            m0 = fmaf(c, fa.x, m0); m1 = fmaf(c, fa.y, m1);
            m2 = fmaf(c, fb.x, m2); m3 = fmaf(c, fb.y, m3);
        }
    }
    {
        const int lo = base + q * (NMQ/4), hi = lo + (NMQ/4);
        #pragma unroll 4
        for (int t = lo; t < hi; ++t) {
            uint4 r = __ldg(&g_rec5[t]);
            unsigned o0 = (r.x << 8) & 0xFF00u, o1 = r.x & 0xFF00u;
            unsigned o2 = (r.x >> 8) & 0xFF00u, o3 = (r.x >> 16) & 0xFF00u, o4 = r.y << 8;
            uint2 u0 = *(const uint2*)(xb+o0), u1 = *(const uint2*)(xb+o1);
            uint2 u2 = *(const uint2*)(xb+o2), u3 = *(const uint2*)(xb+o3), u4 = *(const uint2*)(xb+o4);
            __half2 pa = __hmul2(__hmul2(__hmul2(as_h2(u0.x), as_h2(u1.x)), __hmul2(as_h2(u2.x), as_h2(u3.x))), as_h2(u4.x));
            __half2 pb = __hmul2(__hmul2(__hmul2(as_h2(u0.y), as_h2(u1.y)), __hmul2(as_h2(u2.y), as_h2(u3.y))), as_h2(u4.y));
            float2 fa = __half22float2(pa), fb = __half22float2(pb);
            float c = __uint_as_float(r.z);
            m0 = fmaf(c, fa.x, m0); m1 = fmaf(c, fa.y, m1);
            m2 = fmaf(c, fb.x, m2); m3 = fmaf(c, fb.y, m3);
        }
    }

    *(float4*)&s_redf[q][4 * gg] = make_float4(m0, m1, m2, m3);
    __syncthreads();

    {
        float r = s_redf[0][tid] + s_redf[1][tid] + s_redf[2][tid] + s_redf[3][tid];
        atomicAdd(out + (size_t)tile * TROWS + tid, r);
    }

    // self-reset for graph replay: 8th consumer zeroes the tile's counters
    __threadfence();
    __syncthreads();
    if (tid == 0) {
        int v = atomicAdd(&g_fin[tile], 1);
        if (v == 7) {
            g_cnt[tile] = 0;
            g_fin[tile] = 0;
            __threadfence();
        }
    }
}

extern "C" void kernel_launch(void* const* d_in, const int* in_sizes, int n_in,
                              void* d_out, int out_size)
{
    const float* x    = (const float*)d_in[0];
    const int*   S    = (const int*)  d_in[1];
    const float* a    = (const float*)d_in[2];
    const float* b    = (const float*)d_in[3];
    const int*   idx3 = (const int*)  d_in[4];
    const float* c3   = (const float*)d_in[5];
    const int*   idx4 = (const int*)  d_in[6];
    const float* c4   = (const float*)d_in[7];
    const int*   idx5 = (const int*)  d_in[8];
    const float* c5   = (const float*)d_in[9];
    float* out = (float*)d_out;

    fused_kernel<<<NCTA, TPB>>>(x, out, b, S, a, idx3, c3, idx4, c4, idx5, c5);
}